// round 1
// baseline (speedup 1.0000x reference)
#include <cuda_runtime.h>
#include <cuda_bf16.h>
#include <math.h>

#define NTOK   131072
#define DIMD   256
#define NEXP   8
#define CAPE   20480
#define NCHUNK 128      // NTOK / 1024

// ---------------- device scratch (allocation-free: __device__ globals) -------
__device__ float g_x75 [(size_t)NTOK * 75];
__device__ float g_h   [(size_t)NTOK * 256];
__device__ float g_t1  [(size_t)NTOK * 256];
__device__ float g_ext [(size_t)NTOK * 256];
__device__ float g_disp[(size_t)NEXP * CAPE * 512];
__device__ float g_p   [(size_t)NEXP * CAPE * 256];
__device__ float g_q   [(size_t)NEXP * CAPE * 256];
__device__ float g_f331[(size_t)NTOK * 331];
__device__ float g_f128[(size_t)NTOK * 128];
__device__ int   g_eidx[NTOK];
__device__ float g_gate[NTOK];
__device__ int   g_loc [NTOK];
__device__ int   g_ccnt[NCHUNK * NEXP];
__device__ int   g_coff[NCHUNK * NEXP];
__device__ int   g_cnt [NEXP];

// ---------------- featurize: posenc(xyz,12) -> x75, posenc(dir,4)+emb -> f331 tail
__global__ void featurize_kernel(const float* __restrict__ x,
                                 const float* __restrict__ emb_a,
                                 float* __restrict__ x75,
                                 float* __restrict__ f331)
{
    int i = blockIdx.x * blockDim.x + threadIdx.x;
    if (i >= NTOK) return;
    const float* xi = x + (size_t)i * 7;
    float p0 = xi[0], p1 = xi[1], p2 = xi[2];
    float* o = x75 + (size_t)i * 75;
    o[0] = p0; o[1] = p1; o[2] = p2;
    float f = 1.0f;
    #pragma unroll
    for (int k = 0; k < 12; k++) {
        float* w = o + 3 + k * 6;
        w[0] = sinf(p0 * f); w[1] = sinf(p1 * f); w[2] = sinf(p2 * f);
        w[3] = cosf(p0 * f); w[4] = cosf(p1 * f); w[5] = cosf(p2 * f);
        f *= 2.0f;
    }
    float d0 = xi[3], d1 = xi[4], d2 = xi[5];
    float* qv = f331 + (size_t)i * 331 + 256;
    qv[0] = d0; qv[1] = d1; qv[2] = d2;
    f = 1.0f;
    #pragma unroll
    for (int k = 0; k < 4; k++) {
        float* w = qv + 3 + k * 6;
        w[0] = sinf(d0 * f); w[1] = sinf(d1 * f); w[2] = sinf(d2 * f);
        w[3] = cosf(d0 * f); w[4] = cosf(d1 * f); w[5] = cosf(d2 * f);
        f *= 2.0f;
    }
    int app = (int)xi[6];
    const float* em = emb_a + (size_t)app * 48;
    float* eo = f331 + (size_t)i * 331 + 283;
    #pragma unroll
    for (int c = 0; c < 48; c++) eo[c] = em[c];
}

// ---------------- generic tiled fp32 GEMM: C = A[M,K] @ B[K,N] + bias, opt relu
#define BM 64
#define BN 64
#define BK 16

__device__ __forceinline__ void gemm_tile(
    const float* __restrict__ A, int lda,
    const float* __restrict__ B, int ldb,
    const float* __restrict__ bias,
    float* __restrict__ C, int ldc,
    int M, int N, int K, int relu, int m0, int n0)
{
    __shared__ float As[BK][BM + 4];
    __shared__ float Bs[BK][BN];
    int tid = threadIdx.x;
    int tx = tid & 15, ty = tid >> 4;
    float acc[4][4];
    #pragma unroll
    for (int i = 0; i < 4; i++)
        #pragma unroll
        for (int j = 0; j < 4; j++) acc[i][j] = 0.0f;

    for (int k0 = 0; k0 < K; k0 += BK) {
        #pragma unroll
        for (int r = 0; r < 4; r++) {
            int idx = tid + r * 256;
            int m = idx >> 4, kk = idx & 15;
            int gm = m0 + m, gk = k0 + kk;
            As[kk][m] = (gm < M && gk < K) ? A[(size_t)gm * lda + gk] : 0.0f;
        }
        #pragma unroll
        for (int r = 0; r < 4; r++) {
            int idx = tid + r * 256;
            int kk = idx >> 6, n = idx & 63;
            int gk = k0 + kk, gn = n0 + n;
            Bs[kk][n] = (gk < K && gn < N) ? B[(size_t)gk * ldb + gn] : 0.0f;
        }
        __syncthreads();
        #pragma unroll
        for (int kk = 0; kk < BK; kk++) {
            float a[4], b[4];
            #pragma unroll
            for (int i = 0; i < 4; i++) a[i] = As[kk][ty * 4 + i];
            #pragma unroll
            for (int j = 0; j < 4; j++) b[j] = Bs[kk][tx * 4 + j];
            #pragma unroll
            for (int i = 0; i < 4; i++)
                #pragma unroll
                for (int j = 0; j < 4; j++) acc[i][j] += a[i] * b[j];
        }
        __syncthreads();
    }
    #pragma unroll
    for (int i = 0; i < 4; i++) {
        int gm = m0 + ty * 4 + i;
        if (gm >= M) continue;
        #pragma unroll
        for (int j = 0; j < 4; j++) {
            int gn = n0 + tx * 4 + j;
            if (gn >= N) continue;
            float v = acc[i][j] + bias[gn];
            if (relu) v = fmaxf(v, 0.0f);
            C[(size_t)gm * ldc + gn] = v;
        }
    }
}

__global__ void gemm_kernel(const float* __restrict__ A, int lda,
                            const float* __restrict__ B, int ldb,
                            const float* __restrict__ bias,
                            float* __restrict__ C, int ldc,
                            int M, int N, int K, int relu)
{
    gemm_tile(A, lda, B, ldb, bias, C, ldc, M, N, K, relu,
              blockIdx.x * BM, blockIdx.y * BN);
}

// Grouped per-expert GEMM. Blocks self-prune against device-side counts, so
// the launch geometry is fixed (graph-capturable).
__global__ void gemm_moe_kernel(const float* __restrict__ Abase, int lda,
                                const float* __restrict__ Bbase, long long bstride, int ldb,
                                const float* __restrict__ biasBase, int biasStride,
                                float* __restrict__ Cbase, int ldc,
                                int Ncols, int K, int relu)
{
    int e = blockIdx.z;
    int Me = min(g_cnt[e], CAPE);
    int m0 = blockIdx.x * BM;
    if (m0 >= Me) return;
    const float* A = Abase + (size_t)e * CAPE * lda;
    float* C = Cbase + (size_t)e * CAPE * ldc;
    const float* B = Bbase + (size_t)e * bstride;
    const float* bias = biasBase + (size_t)e * biasStride;
    gemm_tile(A, lda, B, ldb, bias, C, ldc, Me, Ncols, K, relu,
              m0, blockIdx.y * BN);
}

// ---------------- layernorm (in place), one block per row
__global__ void layernorm_kernel(float* __restrict__ xio,
                                 const float* __restrict__ g,
                                 const float* __restrict__ b)
{
    int row = blockIdx.x;
    int tid = threadIdx.x;
    int lane = tid & 31, wid = tid >> 5;
    float v = xio[(size_t)row * 256 + tid];
    __shared__ float red[8];
    __shared__ float sh_mean, sh_rstd;
    float s = v;
    #pragma unroll
    for (int o = 16; o > 0; o >>= 1) s += __shfl_xor_sync(0xffffffffu, s, o);
    if (lane == 0) red[wid] = s;
    __syncthreads();
    if (tid == 0) {
        float t = 0.0f;
        #pragma unroll
        for (int i = 0; i < 8; i++) t += red[i];
        sh_mean = t * (1.0f / 256.0f);
    }
    __syncthreads();
    float d = v - sh_mean;
    float qv = d * d;
    #pragma unroll
    for (int o = 16; o > 0; o >>= 1) qv += __shfl_xor_sync(0xffffffffu, qv, o);
    if (lane == 0) red[wid] = qv;
    __syncthreads();
    if (tid == 0) {
        float t = 0.0f;
        #pragma unroll
        for (int i = 0; i < 8; i++) t += red[i];
        sh_rstd = rsqrtf(t * (1.0f / 256.0f) + 1e-5f);
    }
    __syncthreads();
    xio[(size_t)row * 256 + tid] = d * sh_rstd * g[tid] + b[tid];
}

// ---------------- gating: logits = G @ wg (256x8), softmax max-prob + argmax
__global__ void gate_kernel(const float* __restrict__ G,
                            const float* __restrict__ wg,
                            int* __restrict__ eidx,
                            float* __restrict__ gate)
{
    int token = blockIdx.x * 8 + (threadIdx.x >> 5);
    int lane = threadIdx.x & 31;
    const float* row = G + (size_t)token * 256;
    float acc[8];
    #pragma unroll
    for (int e = 0; e < 8; e++) acc[e] = 0.0f;
    for (int c = lane; c < 256; c += 32) {
        float gv = row[c];
        #pragma unroll
        for (int e = 0; e < 8; e++) acc[e] += gv * wg[c * 8 + e];
    }
    #pragma unroll
    for (int e = 0; e < 8; e++)
        #pragma unroll
        for (int o = 16; o > 0; o >>= 1) acc[e] += __shfl_xor_sync(0xffffffffu, acc[e], o);
    if (lane == 0) {
        int best = 0; float bv = acc[0];
        #pragma unroll
        for (int e = 1; e < 8; e++) if (acc[e] > bv) { bv = acc[e]; best = e; }
        float sum = 0.0f;
        #pragma unroll
        for (int e = 0; e < 8; e++) sum += expf(acc[e] - bv);
        eidx[token] = best;
        gate[token] = 1.0f / sum;   // softmax value at the argmax
    }
}

// ---------------- deterministic per-expert ranking (reproduces cumsum order)
__global__ void count_kernel(const int* __restrict__ eidx, int* __restrict__ ccnt)
{
    __shared__ int c[8];
    if (threadIdx.x < 8) c[threadIdx.x] = 0;
    __syncthreads();
    int base = blockIdx.x * 1024;
    for (int t = threadIdx.x; t < 1024; t += 256)
        atomicAdd(&c[eidx[base + t]], 1);
    __syncthreads();
    if (threadIdx.x < 8) ccnt[blockIdx.x * 8 + threadIdx.x] = c[threadIdx.x];
}

__global__ void scan_kernel(const int* __restrict__ ccnt, int* __restrict__ coff,
                            int* __restrict__ cnt)
{
    int e = threadIdx.x;   // 8 threads
    int run = 0;
    for (int ch = 0; ch < NCHUNK; ch++) {
        coff[ch * 8 + e] = run;
        run += ccnt[ch * 8 + e];
    }
    cnt[e] = run;
}

__global__ void rank_kernel(const int* __restrict__ eidx,
                            const int* __restrict__ coff,
                            int* __restrict__ loc)
{
    __shared__ int se[1024];
    __shared__ int sl[1024];
    __shared__ int c[8];
    int base = blockIdx.x * 1024;
    for (int t = threadIdx.x; t < 1024; t += 256) se[t] = eidx[base + t];
    if (threadIdx.x < 8) c[threadIdx.x] = coff[blockIdx.x * 8 + threadIdx.x];
    __syncthreads();
    if (threadIdx.x == 0) {
        for (int t = 0; t < 1024; t++) { int e = se[t]; sl[t] = c[e]++; }
    }
    __syncthreads();
    for (int t = threadIdx.x; t < 1024; t += 256) loc[base + t] = sl[t];
}

// ---------------- dispatch: copy h row into per-expert slot (cols 0:256 of 512-wide)
__global__ void dispatch_kernel(const float* __restrict__ H,
                                const int* __restrict__ eidx,
                                const int* __restrict__ loc,
                                float* __restrict__ disp)
{
    int token = blockIdx.x * 8 + (threadIdx.x >> 5);
    int lane = threadIdx.x & 31;
    int l = loc[token];
    if (l >= CAPE) return;
    int e = eidx[token];
    const float4* src = (const float4*)(H + (size_t)token * 256);
    float4* dst = (float4*)(disp + ((size_t)e * CAPE + l) * 512);
    dst[lane]      = src[lane];
    dst[lane + 32] = src[lane + 32];
}

// ---------------- gather: y = keep ? q*gate : 0; relu; sigma = softplus(y.ws+bs)
__global__ void gather_kernel(const float* __restrict__ Q,
                              const int* __restrict__ eidx,
                              const int* __restrict__ loc,
                              const float* __restrict__ gate,
                              const float* __restrict__ ws,
                              const float* __restrict__ bs,
                              float* __restrict__ HM,
                              float* __restrict__ out)
{
    int token = blockIdx.x * 8 + (threadIdx.x >> 5);
    int lane = threadIdx.x & 31;
    int l = loc[token];
    int e = eidx[token];
    float gv = gate[token];
    bool keep = (l < CAPE);
    const float* src = Q + ((size_t)e * CAPE + (keep ? l : 0)) * 256;
    float* dstrow = HM + (size_t)token * 256;
    float dot = 0.0f;
    for (int c = lane; c < 256; c += 32) {
        float v = keep ? src[c] * gv : 0.0f;
        v = fmaxf(v, 0.0f);
        dstrow[c] = v;
        dot += v * ws[c];
    }
    #pragma unroll
    for (int o = 16; o > 0; o >>= 1) dot += __shfl_xor_sync(0xffffffffu, dot, o);
    if (lane == 0) {
        float t = dot + bs[0];
        float sp = fmaxf(t, 0.0f) + log1pf(expf(-fabsf(t)));
        out[(size_t)token * 4 + 3] = sp;
    }
}

// ---------------- rgb: sigmoid(f128 @ wc + bc)
__global__ void rgb_kernel(const float* __restrict__ F,
                           const float* __restrict__ wc,
                           const float* __restrict__ bc,
                           float* __restrict__ out)
{
    int token = blockIdx.x * 8 + (threadIdx.x >> 5);
    int lane = threadIdx.x & 31;
    const float* row = F + (size_t)token * 128;
    float a0 = 0.0f, a1 = 0.0f, a2 = 0.0f;
    for (int c = lane; c < 128; c += 32) {
        float v = row[c];
        a0 += v * wc[c * 3 + 0];
        a1 += v * wc[c * 3 + 1];
        a2 += v * wc[c * 3 + 2];
    }
    #pragma unroll
    for (int o = 16; o > 0; o >>= 1) {
        a0 += __shfl_xor_sync(0xffffffffu, a0, o);
        a1 += __shfl_xor_sync(0xffffffffu, a1, o);
        a2 += __shfl_xor_sync(0xffffffffu, a2, o);
    }
    if (lane == 0) {
        out[(size_t)token * 4 + 0] = 1.0f / (1.0f + expf(-(a0 + bc[0])));
        out[(size_t)token * 4 + 1] = 1.0f / (1.0f + expf(-(a1 + bc[1])));
        out[(size_t)token * 4 + 2] = 1.0f / (1.0f + expf(-(a2 + bc[2])));
    }
}

// ============================================================================
extern "C" void kernel_launch(void* const* d_in, const int* in_sizes, int n_in,
                              void* d_out, int out_size)
{
    const float* x     = (const float*)d_in[0];
    const float* emb_a = (const float*)d_in[1];
    const float* w_xyz = (const float*)d_in[2];
    const float* b_xyz = (const float*)d_in[3];
    const float* wg1   = (const float*)d_in[4];
    const float* bg1   = (const float*)d_in[5];
    const float* wg2   = (const float*)d_in[6];
    const float* bg2   = (const float*)d_in[7];
    const float* ln_g  = (const float*)d_in[8];
    const float* ln_b  = (const float*)d_in[9];
    const float* wg    = (const float*)d_in[10];
    const float* eW_a  = (const float*)d_in[11];
    const float* eb_a  = (const float*)d_in[12];
    const float* eW3   = (const float*)d_in[13];
    const float* eb3   = (const float*)d_in[14];
    const float* eW_b  = (const float*)d_in[15];
    const float* eb_b  = (const float*)d_in[16];
    const float* w1    = (const float*)d_in[17];
    const float* b1    = (const float*)d_in[18];
    const float* w2    = (const float*)d_in[19];
    const float* b2    = (const float*)d_in[20];
    const float* ws    = (const float*)d_in[21];
    const float* bs    = (const float*)d_in[22];
    const float* wc    = (const float*)d_in[23];
    const float* bc    = (const float*)d_in[24];
    float* out = (float*)d_out;

    float *x75, *h, *t1, *ext, *disp, *p, *q, *f331, *f128, *gate;
    int *eidx, *loc, *ccnt, *coff, *cnt;
    cudaGetSymbolAddress((void**)&x75,  g_x75);
    cudaGetSymbolAddress((void**)&h,    g_h);
    cudaGetSymbolAddress((void**)&t1,   g_t1);
    cudaGetSymbolAddress((void**)&ext,  g_ext);
    cudaGetSymbolAddress((void**)&disp, g_disp);
    cudaGetSymbolAddress((void**)&p,    g_p);
    cudaGetSymbolAddress((void**)&q,    g_q);
    cudaGetSymbolAddress((void**)&f331, g_f331);
    cudaGetSymbolAddress((void**)&f128, g_f128);
    cudaGetSymbolAddress((void**)&gate, g_gate);
    cudaGetSymbolAddress((void**)&eidx, g_eidx);
    cudaGetSymbolAddress((void**)&loc,  g_loc);
    cudaGetSymbolAddress((void**)&ccnt, g_ccnt);
    cudaGetSymbolAddress((void**)&coff, g_coff);
    cudaGetSymbolAddress((void**)&cnt,  g_cnt);

    // 1) featurize
    featurize_kernel<<<NTOK / 256, 256>>>(x, emb_a, x75, f331);

    // 2) backbone GEMMs
    dim3 gBig(NTOK / BM, 256 / BN);   // (2048, 4)
    gemm_kernel<<<gBig, 256>>>(x75, 75, w_xyz, 256, b_xyz, h,   256, NTOK, 256, 75, 0);
    gemm_kernel<<<gBig, 256>>>(h,  256, wg1,   256, bg1,   t1,  256, NTOK, 256, 256, 1);
    gemm_kernel<<<gBig, 256>>>(t1, 256, wg2,   256, bg2,   ext, 256, NTOK, 256, 256, 0);

    // 3) layernorm + gating
    layernorm_kernel<<<NTOK, 256>>>(ext, ln_g, ln_b);
    gate_kernel<<<NTOK / 8, 256>>>(ext, wg, eidx, gate);

    // 4) deterministic ranking + dispatch
    count_kernel<<<NCHUNK, 256>>>(eidx, ccnt);
    scan_kernel<<<1, 8>>>(ccnt, coff, cnt);
    rank_kernel<<<NCHUNK, 256>>>(eidx, coff, loc);
    dispatch_kernel<<<NTOK / 8, 256>>>(h, eidx, loc, disp);

    // 5) expert MLP (grouped GEMMs), weights: eW_a[e,i] at (e*3+i)*65536
    dim3 gMoe(CAPE / BM, 256 / BN, NEXP);  // (320, 4, 8)
    gemm_moe_kernel<<<gMoe, 256>>>(disp, 512, eW_a + 0 * 65536, 3LL * 65536, 256,
                                   eb_a + 0 * 256, 768, p, 256, 256, 256, 1);
    gemm_moe_kernel<<<gMoe, 256>>>(p, 256, eW_a + 1 * 65536, 3LL * 65536, 256,
                                   eb_a + 1 * 256, 768, q, 256, 256, 256, 1);
    gemm_moe_kernel<<<gMoe, 256>>>(q, 256, eW_a + 2 * 65536, 3LL * 65536, 256,
                                   eb_a + 2 * 256, 768, disp + 256, 512, 256, 256, 1);
    gemm_moe_kernel<<<gMoe, 256>>>(disp, 512, eW3, 512LL * 256, 256,
                                   eb3, 256, p, 256, 256, 512, 1);
    gemm_moe_kernel<<<gMoe, 256>>>(p, 256, eW_b + 0 * 65536, 3LL * 65536, 256,
                                   eb_b + 0 * 256, 768, q, 256, 256, 256, 1);
    gemm_moe_kernel<<<gMoe, 256>>>(q, 256, eW_b + 1 * 65536, 3LL * 65536, 256,
                                   eb_b + 1 * 256, 768, p, 256, 256, 256, 1);
    gemm_moe_kernel<<<gMoe, 256>>>(p, 256, eW_b + 2 * 65536, 3LL * 65536, 256,
                                   eb_b + 2 * 256, 768, q, 256, 256, 256, 0);

    // 6) gather + gate + relu + sigma (reuses g_h as post-MoE activations)
    gather_kernel<<<NTOK / 8, 256>>>(q, eidx, loc, gate, ws, bs, h, out);

    // 7) head
    gemm_kernel<<<gBig, 256>>>(h, 256, w1, 256, b1, f331, 331, NTOK, 256, 256, 0);
    dim3 g2(NTOK / BM, 128 / BN);     // (2048, 2)
    gemm_kernel<<<g2, 256>>>(f331, 331, w2, 128, b2, f128, 128, NTOK, 128, 331, 1);
    rgb_kernel<<<NTOK / 8, 256>>>(f128, wc, bc, out);
}

// round 3
// speedup vs baseline: 1.3965x; 1.3965x over previous
#include <cuda_runtime.h>
#include <cuda_bf16.h>
#include <cstdint>
#include <math.h>

#define NTOK   131072
#define DIMD   256
#define NEXP   8
#define CAPE   20480
#define NCHUNK 128      // NTOK / 1024

// ---------------- device scratch (allocation-free: __device__ globals) -------
__device__ float g_x75 [(size_t)NTOK * 75];
__device__ float g_h   [(size_t)NTOK * 256];
__device__ float g_t1  [(size_t)NTOK * 256];
__device__ float g_ext [(size_t)NTOK * 256];
__device__ float g_disp[(size_t)NEXP * CAPE * 512];
__device__ float g_p   [(size_t)NEXP * CAPE * 256];
__device__ float g_q   [(size_t)NEXP * CAPE * 256];
__device__ float g_f331[(size_t)NTOK * 331];
__device__ float g_f128[(size_t)NTOK * 128];
__device__ int   g_eidx[NTOK];
__device__ float g_gate[NTOK];
__device__ int   g_loc [NTOK];
__device__ int   g_ccnt[NCHUNK * NEXP];
__device__ int   g_coff[NCHUNK * NEXP];
__device__ int   g_cnt [NEXP];

// ---------------- featurize ------------------------------------------------
__global__ void featurize_kernel(const float* __restrict__ x,
                                 const float* __restrict__ emb_a,
                                 float* __restrict__ x75,
                                 float* __restrict__ f331)
{
    int i = blockIdx.x * blockDim.x + threadIdx.x;
    if (i >= NTOK) return;
    const float* xi = x + (size_t)i * 7;
    float p0 = xi[0], p1 = xi[1], p2 = xi[2];
    float* o = x75 + (size_t)i * 75;
    o[0] = p0; o[1] = p1; o[2] = p2;
    float f = 1.0f;
    #pragma unroll
    for (int k = 0; k < 12; k++) {
        float* w = o + 3 + k * 6;
        w[0] = sinf(p0 * f); w[1] = sinf(p1 * f); w[2] = sinf(p2 * f);
        w[3] = cosf(p0 * f); w[4] = cosf(p1 * f); w[5] = cosf(p2 * f);
        f *= 2.0f;
    }
    float d0 = xi[3], d1 = xi[4], d2 = xi[5];
    float* qv = f331 + (size_t)i * 331 + 256;
    qv[0] = d0; qv[1] = d1; qv[2] = d2;
    f = 1.0f;
    #pragma unroll
    for (int k = 0; k < 4; k++) {
        float* w = qv + 3 + k * 6;
        w[0] = sinf(d0 * f); w[1] = sinf(d1 * f); w[2] = sinf(d2 * f);
        w[3] = cosf(d0 * f); w[4] = cosf(d1 * f); w[5] = cosf(d2 * f);
        f *= 2.0f;
    }
    int app = (int)xi[6];
    const float* em = emb_a + (size_t)app * 48;
    float* eo = f331 + (size_t)i * 331 + 283;
    #pragma unroll
    for (int c = 0; c < 48; c++) eo[c] = em[c];
}

// ---------------- TF32 tensor-core GEMM ------------------------------------
// CTA tile 128x128, BK = 32 (FAST) or 16 (PRECISE = 3xTF32 hi/lo split).
// 8 warps in 4(m) x 2(n); warp tile 32x64; mma.sync.m16n8k8 tf32.

__device__ __forceinline__ uint32_t f2tf32(float v) {
    uint32_t u;
    asm("cvt.rna.tf32.f32 %0, %1;" : "=r"(u) : "f"(v));
    return u;
}

__device__ __forceinline__ void mma_tf32(float c[4], const uint32_t a[4],
                                         const uint32_t b[2]) {
    asm volatile(
        "mma.sync.aligned.m16n8k8.row.col.f32.tf32.tf32.f32 "
        "{%0,%1,%2,%3}, {%4,%5,%6,%7}, {%8,%9}, {%0,%1,%2,%3};\n"
        : "+f"(c[0]), "+f"(c[1]), "+f"(c[2]), "+f"(c[3])
        : "r"(a[0]), "r"(a[1]), "r"(a[2]), "r"(a[3]), "r"(b[0]), "r"(b[1]));
}

template<int PRECISE>
__device__ __forceinline__ void mma_tile(
    const float* __restrict__ A, int lda,
    const float* __restrict__ B, int ldb,
    const float* __restrict__ bias,
    float* __restrict__ C, int ldc,
    int M, int N, int K, int relu, int m0, int n0)
{
    constexpr int BKv = PRECISE ? 16 : 32;
    __shared__ uint32_t Ah[BKv][132];
    __shared__ uint32_t Bh[BKv][132];
    __shared__ uint32_t Al[PRECISE ? BKv : 1][PRECISE ? 132 : 1];
    __shared__ uint32_t Bl[PRECISE ? BKv : 1][PRECISE ? 132 : 1];

    int tid = threadIdx.x;
    int wid = tid >> 5, lane = tid & 31;
    int wm = (wid >> 1) * 32;      // warp m offset within CTA tile
    int wn = (wid & 1) * 64;       // warp n offset
    int gid = lane >> 2, tig = lane & 3;

    float acc[2][8][4] = {};

    for (int k0 = 0; k0 < K; k0 += BKv) {
        // ---- stage A [BKv x 128] transposed, with tf32 (+residual) ----
        #pragma unroll
        for (int r = 0; r < (128 * BKv) / 256; r++) {
            int idx = tid + r * 256;
            int m = idx / BKv, kk = idx % BKv;
            int gm = m0 + m, gk = k0 + kk;
            float v = (gm < M && gk < K) ? A[(size_t)gm * lda + gk] : 0.0f;
            uint32_t hv = f2tf32(v);
            Ah[kk][m] = hv;
            if (PRECISE) Al[kk][m] = f2tf32(v - __uint_as_float(hv));
        }
        // ---- stage B [BKv x 128] ----
        #pragma unroll
        for (int r = 0; r < (128 * BKv) / 256; r++) {
            int idx = tid + r * 256;
            int kk = idx >> 7, n = idx & 127;
            int gk = k0 + kk, gn = n0 + n;
            float v = (gk < K && gn < N) ? B[(size_t)gk * ldb + gn] : 0.0f;
            uint32_t hv = f2tf32(v);
            Bh[kk][n] = hv;
            if (PRECISE) Bl[kk][n] = f2tf32(v - __uint_as_float(hv));
        }
        __syncthreads();

        #pragma unroll
        for (int kk = 0; kk < BKv; kk += 8) {
            uint32_t a[2][4], b[8][2];
            #pragma unroll
            for (int i = 0; i < 2; i++) {
                int m = wm + i * 16 + gid;
                a[i][0] = Ah[kk + tig][m];
                a[i][1] = Ah[kk + tig][m + 8];
                a[i][2] = Ah[kk + tig + 4][m];
                a[i][3] = Ah[kk + tig + 4][m + 8];
            }
            #pragma unroll
            for (int j = 0; j < 8; j++) {
                int n = wn + j * 8 + gid;
                b[j][0] = Bh[kk + tig][n];
                b[j][1] = Bh[kk + tig + 4][n];
            }
            if (PRECISE) {
                uint32_t al[2][4], bl[8][2];
                #pragma unroll
                for (int i = 0; i < 2; i++) {
                    int m = wm + i * 16 + gid;
                    al[i][0] = Al[kk + tig][m];
                    al[i][1] = Al[kk + tig][m + 8];
                    al[i][2] = Al[kk + tig + 4][m];
                    al[i][3] = Al[kk + tig + 4][m + 8];
                }
                #pragma unroll
                for (int j = 0; j < 8; j++) {
                    int n = wn + j * 8 + gid;
                    bl[j][0] = Bl[kk + tig][n];
                    bl[j][1] = Bl[kk + tig + 4][n];
                }
                #pragma unroll
                for (int i = 0; i < 2; i++)
                    #pragma unroll
                    for (int j = 0; j < 8; j++) {
                        mma_tf32(acc[i][j], al[i], b[j]);   // lo*hi
                        mma_tf32(acc[i][j], a[i], bl[j]);   // hi*lo
                    }
            }
            #pragma unroll
            for (int i = 0; i < 2; i++)
                #pragma unroll
                for (int j = 0; j < 8; j++)
                    mma_tf32(acc[i][j], a[i], b[j]);        // hi*hi
        }
        __syncthreads();
    }

    // ---- epilogue: bias + optional relu ----
    #pragma unroll
    for (int i = 0; i < 2; i++) {
        int r0 = m0 + wm + i * 16 + gid;
        int r1 = r0 + 8;
        #pragma unroll
        for (int j = 0; j < 8; j++) {
            int col = n0 + wn + j * 8 + tig * 2;
            float b0v = (col < N) ? bias[col] : 0.0f;
            float b1v = (col + 1 < N) ? bias[col + 1] : 0.0f;
            if (r0 < M && col < N) {
                float v = acc[i][j][0] + b0v;
                if (relu) v = fmaxf(v, 0.0f);
                C[(size_t)r0 * ldc + col] = v;
            }
            if (r0 < M && col + 1 < N) {
                float v = acc[i][j][1] + b1v;
                if (relu) v = fmaxf(v, 0.0f);
                C[(size_t)r0 * ldc + col + 1] = v;
            }
            if (r1 < M && col < N) {
                float v = acc[i][j][2] + b0v;
                if (relu) v = fmaxf(v, 0.0f);
                C[(size_t)r1 * ldc + col] = v;
            }
            if (r1 < M && col + 1 < N) {
                float v = acc[i][j][3] + b1v;
                if (relu) v = fmaxf(v, 0.0f);
                C[(size_t)r1 * ldc + col + 1] = v;
            }
        }
    }
}

template<int PRECISE>
__global__ void __launch_bounds__(256) mma_gemm_kernel(
    const float* __restrict__ A, int lda,
    const float* __restrict__ B, int ldb,
    const float* __restrict__ bias,
    float* __restrict__ C, int ldc,
    int M, int N, int K, int relu)
{
    mma_tile<PRECISE>(A, lda, B, ldb, bias, C, ldc, M, N, K, relu,
                      blockIdx.x * 128, blockIdx.y * 128);
}

// Grouped per-expert GEMM; fixed geometry, self-prunes against device counts.
__global__ void __launch_bounds__(256) mma_moe_kernel(
    const float* __restrict__ Abase, int lda,
    const float* __restrict__ Bbase, long long bstride, int ldb,
    const float* __restrict__ biasBase, int biasStride,
    float* __restrict__ Cbase, int ldc,
    int Ncols, int K, int relu)
{
    int e = blockIdx.z;
    int Me = min(g_cnt[e], CAPE);
    int m0 = blockIdx.x * 128;
    if (m0 >= Me) return;
    const float* A = Abase + (size_t)e * CAPE * lda;
    float* C = Cbase + (size_t)e * CAPE * ldc;
    const float* B = Bbase + (size_t)e * bstride;
    const float* bias = biasBase + (size_t)e * biasStride;
    mma_tile<0>(A, lda, B, ldb, bias, C, ldc, Me, Ncols, K, relu,
                m0, blockIdx.y * 128);
}

// ---------------- layernorm (in place), one block per row -------------------
__global__ void layernorm_kernel(float* __restrict__ xio,
                                 const float* __restrict__ g,
                                 const float* __restrict__ b)
{
    int row = blockIdx.x;
    int tid = threadIdx.x;
    int lane = tid & 31, wid = tid >> 5;
    float v = xio[(size_t)row * 256 + tid];
    __shared__ float red[8];
    __shared__ float sh_mean, sh_rstd;
    float s = v;
    #pragma unroll
    for (int o = 16; o > 0; o >>= 1) s += __shfl_xor_sync(0xffffffffu, s, o);
    if (lane == 0) red[wid] = s;
    __syncthreads();
    if (tid == 0) {
        float t = 0.0f;
        #pragma unroll
        for (int i = 0; i < 8; i++) t += red[i];
        sh_mean = t * (1.0f / 256.0f);
    }
    __syncthreads();
    float d = v - sh_mean;
    float qv = d * d;
    #pragma unroll
    for (int o = 16; o > 0; o >>= 1) qv += __shfl_xor_sync(0xffffffffu, qv, o);
    if (lane == 0) red[wid] = qv;
    __syncthreads();
    if (tid == 0) {
        float t = 0.0f;
        #pragma unroll
        for (int i = 0; i < 8; i++) t += red[i];
        sh_rstd = rsqrtf(t * (1.0f / 256.0f) + 1e-5f);
    }
    __syncthreads();
    xio[(size_t)row * 256 + tid] = d * sh_rstd * g[tid] + b[tid];
}

// ---------------- gating ----------------------------------------------------
__global__ void gate_kernel(const float* __restrict__ G,
                            const float* __restrict__ wg,
                            int* __restrict__ eidx,
                            float* __restrict__ gate)
{
    int token = blockIdx.x * 8 + (threadIdx.x >> 5);
    int lane = threadIdx.x & 31;
    const float* row = G + (size_t)token * 256;
    float acc[8];
    #pragma unroll
    for (int e = 0; e < 8; e++) acc[e] = 0.0f;
    for (int c = lane; c < 256; c += 32) {
        float gv = row[c];
        #pragma unroll
        for (int e = 0; e < 8; e++) acc[e] += gv * wg[c * 8 + e];
    }
    #pragma unroll
    for (int e = 0; e < 8; e++)
        #pragma unroll
        for (int o = 16; o > 0; o >>= 1) acc[e] += __shfl_xor_sync(0xffffffffu, acc[e], o);
    if (lane == 0) {
        int best = 0; float bv = acc[0];
        #pragma unroll
        for (int e = 1; e < 8; e++) if (acc[e] > bv) { bv = acc[e]; best = e; }
        float sum = 0.0f;
        #pragma unroll
        for (int e = 0; e < 8; e++) sum += expf(acc[e] - bv);
        eidx[token] = best;
        gate[token] = 1.0f / sum;
    }
}

// ---------------- deterministic per-expert ranking ---------------------------
__global__ void count_kernel(const int* __restrict__ eidx, int* __restrict__ ccnt)
{
    __shared__ int c[8];
    if (threadIdx.x < 8) c[threadIdx.x] = 0;
    __syncthreads();
    int base = blockIdx.x * 1024;
    for (int t = threadIdx.x; t < 1024; t += 256)
        atomicAdd(&c[eidx[base + t]], 1);
    __syncthreads();
    if (threadIdx.x < 8) ccnt[blockIdx.x * 8 + threadIdx.x] = c[threadIdx.x];
}

__global__ void scan_kernel(const int* __restrict__ ccnt, int* __restrict__ coff,
                            int* __restrict__ cnt)
{
    int e = threadIdx.x;
    int run = 0;
    for (int ch = 0; ch < NCHUNK; ch++) {
        coff[ch * 8 + e] = run;
        run += ccnt[ch * 8 + e];
    }
    cnt[e] = run;
}

__global__ void rank_kernel(const int* __restrict__ eidx,
                            const int* __restrict__ coff,
                            int* __restrict__ loc)
{
    __shared__ int se[1024];
    __shared__ int sl[1024];
    __shared__ int c[8];
    int base = blockIdx.x * 1024;
    for (int t = threadIdx.x; t < 1024; t += 256) se[t] = eidx[base + t];
    if (threadIdx.x < 8) c[threadIdx.x] = coff[blockIdx.x * 8 + threadIdx.x];
    __syncthreads();
    if (threadIdx.x == 0) {
        for (int t = 0; t < 1024; t++) { int e = se[t]; sl[t] = c[e]++; }
    }
    __syncthreads();
    for (int t = threadIdx.x; t < 1024; t += 256) loc[base + t] = sl[t];
}

// ---------------- dispatch ---------------------------------------------------
__global__ void dispatch_kernel(const float* __restrict__ H,
                                const int* __restrict__ eidx,
                                const int* __restrict__ loc,
                                float* __restrict__ disp)
{
    int token = blockIdx.x * 8 + (threadIdx.x >> 5);
    int lane = threadIdx.x & 31;
    int l = loc[token];
    if (l >= CAPE) return;
    int e = eidx[token];
    const float4* src = (const float4*)(H + (size_t)token * 256);
    float4* dst = (float4*)(disp + ((size_t)e * CAPE + l) * 512);
    dst[lane]      = src[lane];
    dst[lane + 32] = src[lane + 32];
}

// ---------------- gather + gate + relu + sigma -------------------------------
__global__ void gather_kernel(const float* __restrict__ Q,
                              const int* __restrict__ eidx,
                              const int* __restrict__ loc,
                              const float* __restrict__ gate,
                              const float* __restrict__ ws,
                              const float* __restrict__ bs,
                              float* __restrict__ HM,
                              float* __restrict__ out)
{
    int token = blockIdx.x * 8 + (threadIdx.x >> 5);
    int lane = threadIdx.x & 31;
    int l = loc[token];
    int e = eidx[token];
    float gv = gate[token];
    bool keep = (l < CAPE);
    const float* src = Q + ((size_t)e * CAPE + (keep ? l : 0)) * 256;
    float* dstrow = HM + (size_t)token * 256;
    float dot = 0.0f;
    for (int c = lane; c < 256; c += 32) {
        float v = keep ? src[c] * gv : 0.0f;
        v = fmaxf(v, 0.0f);
        dstrow[c] = v;
        dot += v * ws[c];
    }
    #pragma unroll
    for (int o = 16; o > 0; o >>= 1) dot += __shfl_xor_sync(0xffffffffu, dot, o);
    if (lane == 0) {
        float t = dot + bs[0];
        float sp = fmaxf(t, 0.0f) + log1pf(expf(-fabsf(t)));
        out[(size_t)token * 4 + 3] = sp;
    }
}

// ---------------- rgb --------------------------------------------------------
__global__ void rgb_kernel(const float* __restrict__ F,
                           const float* __restrict__ wc,
                           const float* __restrict__ bc,
                           float* __restrict__ out)
{
    int token = blockIdx.x * 8 + (threadIdx.x >> 5);
    int lane = threadIdx.x & 31;
    const float* row = F + (size_t)token * 128;
    float a0 = 0.0f, a1 = 0.0f, a2 = 0.0f;
    for (int c = lane; c < 128; c += 32) {
        float v = row[c];
        a0 += v * wc[c * 3 + 0];
        a1 += v * wc[c * 3 + 1];
        a2 += v * wc[c * 3 + 2];
    }
    #pragma unroll
    for (int o = 16; o > 0; o >>= 1) {
        a0 += __shfl_xor_sync(0xffffffffu, a0, o);
        a1 += __shfl_xor_sync(0xffffffffu, a1, o);
        a2 += __shfl_xor_sync(0xffffffffu, a2, o);
    }
    if (lane == 0) {
        out[(size_t)token * 4 + 0] = 1.0f / (1.0f + expf(-(a0 + bc[0])));
        out[(size_t)token * 4 + 1] = 1.0f / (1.0f + expf(-(a1 + bc[1])));
        out[(size_t)token * 4 + 2] = 1.0f / (1.0f + expf(-(a2 + bc[2])));
    }
}

// ============================================================================
extern "C" void kernel_launch(void* const* d_in, const int* in_sizes, int n_in,
                              void* d_out, int out_size)
{
    const float* x     = (const float*)d_in[0];
    const float* emb_a = (const float*)d_in[1];
    const float* w_xyz = (const float*)d_in[2];
    const float* b_xyz = (const float*)d_in[3];
    const float* wg1   = (const float*)d_in[4];
    const float* bg1   = (const float*)d_in[5];
    const float* wg2   = (const float*)d_in[6];
    const float* bg2   = (const float*)d_in[7];
    const float* ln_g  = (const float*)d_in[8];
    const float* ln_b  = (const float*)d_in[9];
    const float* wg    = (const float*)d_in[10];
    const float* eW_a  = (const float*)d_in[11];
    const float* eb_a  = (const float*)d_in[12];
    const float* eW3   = (const float*)d_in[13];
    const float* eb3   = (const float*)d_in[14];
    const float* eW_b  = (const float*)d_in[15];
    const float* eb_b  = (const float*)d_in[16];
    const float* w1    = (const float*)d_in[17];
    const float* b1    = (const float*)d_in[18];
    const float* w2    = (const float*)d_in[19];
    const float* b2    = (const float*)d_in[20];
    const float* ws    = (const float*)d_in[21];
    const float* bs    = (const float*)d_in[22];
    const float* wc    = (const float*)d_in[23];
    const float* bc    = (const float*)d_in[24];
    float* out = (float*)d_out;

    float *x75, *h, *t1, *ext, *disp, *p, *q, *f331, *f128, *gate;
    int *eidx, *loc, *ccnt, *coff, *cnt;
    cudaGetSymbolAddress((void**)&x75,  g_x75);
    cudaGetSymbolAddress((void**)&h,    g_h);
    cudaGetSymbolAddress((void**)&t1,   g_t1);
    cudaGetSymbolAddress((void**)&ext,  g_ext);
    cudaGetSymbolAddress((void**)&disp, g_disp);
    cudaGetSymbolAddress((void**)&p,    g_p);
    cudaGetSymbolAddress((void**)&q,    g_q);
    cudaGetSymbolAddress((void**)&f331, g_f331);
    cudaGetSymbolAddress((void**)&f128, g_f128);
    cudaGetSymbolAddress((void**)&gate, g_gate);
    cudaGetSymbolAddress((void**)&eidx, g_eidx);
    cudaGetSymbolAddress((void**)&loc,  g_loc);
    cudaGetSymbolAddress((void**)&ccnt, g_ccnt);
    cudaGetSymbolAddress((void**)&coff, g_coff);
    cudaGetSymbolAddress((void**)&cnt,  g_cnt);

    // 1) featurize
    featurize_kernel<<<NTOK / 256, 256>>>(x, emb_a, x75, f331);

    // 2) backbone GEMMs (gating-critical path -> 3xTF32 PRECISE)
    dim3 gBig(NTOK / 128, 2);   // (1024, 2)
    mma_gemm_kernel<1><<<gBig, 256>>>(x75, 75, w_xyz, 256, b_xyz, h,   256, NTOK, 256, 75,  0);
    mma_gemm_kernel<1><<<gBig, 256>>>(h,  256, wg1,   256, bg1,   t1,  256, NTOK, 256, 256, 1);
    mma_gemm_kernel<1><<<gBig, 256>>>(t1, 256, wg2,   256, bg2,   ext, 256, NTOK, 256, 256, 0);

    // 3) layernorm + gating
    layernorm_kernel<<<NTOK, 256>>>(ext, ln_g, ln_b);
    gate_kernel<<<NTOK / 8, 256>>>(ext, wg, eidx, gate);

    // 4) deterministic ranking + dispatch
    count_kernel<<<NCHUNK, 256>>>(eidx, ccnt);
    scan_kernel<<<1, 8>>>(ccnt, coff, cnt);
    rank_kernel<<<NCHUNK, 256>>>(eidx, coff, loc);
    dispatch_kernel<<<NTOK / 8, 256>>>(h, eidx, loc, disp);

    // 5) expert MLP (grouped TF32 GEMMs)
    dim3 gMoe(CAPE / 128, 2, NEXP);  // (160, 2, 8)
    mma_moe_kernel<<<gMoe, 256>>>(disp, 512, eW_a + 0 * 65536, 3LL * 65536, 256,
                                  eb_a + 0 * 256, 768, p, 256, 256, 256, 1);
    mma_moe_kernel<<<gMoe, 256>>>(p, 256, eW_a + 1 * 65536, 3LL * 65536, 256,
                                  eb_a + 1 * 256, 768, q, 256, 256, 256, 1);
    mma_moe_kernel<<<gMoe, 256>>>(q, 256, eW_a + 2 * 65536, 3LL * 65536, 256,
                                  eb_a + 2 * 256, 768, disp + 256, 512, 256, 256, 1);
    mma_moe_kernel<<<gMoe, 256>>>(disp, 512, eW3, 512LL * 256, 256,
                                  eb3, 256, p, 256, 256, 512, 1);
    mma_moe_kernel<<<gMoe, 256>>>(p, 256, eW_b + 0 * 65536, 3LL * 65536, 256,
                                  eb_b + 0 * 256, 768, q, 256, 256, 256, 1);
    mma_moe_kernel<<<gMoe, 256>>>(q, 256, eW_b + 1 * 65536, 3LL * 65536, 256,
                                  eb_b + 1 * 256, 768, p, 256, 256, 256, 1);
    mma_moe_kernel<<<gMoe, 256>>>(p, 256, eW_b + 2 * 65536, 3LL * 65536, 256,
                                  eb_b + 2 * 256, 768, q, 256, 256, 256, 0);

    // 6) gather + gate + relu + sigma
    gather_kernel<<<NTOK / 8, 256>>>(q, eidx, loc, gate, ws, bs, h, out);

    // 7) head (FAST TF32)
    mma_gemm_kernel<0><<<gBig, 256>>>(h, 256, w1, 256, b1, f331, 331, NTOK, 256, 256, 0);
    dim3 g2(NTOK / 128, 1);
    mma_gemm_kernel<0><<<g2, 256>>>(f331, 331, w2, 128, b2, f128, 128, NTOK, 128, 331, 1);
    rgb_kernel<<<NTOK / 8, 256>>>(f128, wc, bc, out);
}

// round 4
// speedup vs baseline: 1.6503x; 1.1818x over previous
#include <cuda_runtime.h>
#include <cuda_bf16.h>
#include <cstdint>
#include <math.h>

#define NTOK   131072
#define DIMD   256
#define NEXP   8
#define CAPE   20480
#define NCHUNK 128      // NTOK / 1024

// ---------------- device scratch (allocation-free: __device__ globals) -------
__device__ float g_x75 [(size_t)NTOK * 75];
__device__ float g_h   [(size_t)NTOK * 256];
__device__ float g_t1  [(size_t)NTOK * 256];
__device__ float g_ext [(size_t)NTOK * 256];
__device__ float g_disp[(size_t)NEXP * CAPE * 512];
__device__ float g_p   [(size_t)NEXP * CAPE * 256];
__device__ float g_q   [(size_t)NEXP * CAPE * 256];
__device__ float g_f331[(size_t)NTOK * 331];
__device__ float g_f128[(size_t)NTOK * 128];
__device__ int   g_eidx[NTOK];
__device__ float g_gate[NTOK];
__device__ int   g_loc [NTOK];
__device__ int   g_ccnt[NCHUNK * NEXP];
__device__ int   g_coff[NCHUNK * NEXP];
__device__ int   g_cnt [NEXP];

// ---------------- featurize ------------------------------------------------
__global__ void featurize_kernel(const float* __restrict__ x,
                                 const float* __restrict__ emb_a,
                                 float* __restrict__ x75,
                                 float* __restrict__ f331)
{
    int i = blockIdx.x * blockDim.x + threadIdx.x;
    if (i >= NTOK) return;
    const float* xi = x + (size_t)i * 7;
    float p0 = xi[0], p1 = xi[1], p2 = xi[2];
    float* o = x75 + (size_t)i * 75;
    o[0] = p0; o[1] = p1; o[2] = p2;
    float f = 1.0f;
    #pragma unroll
    for (int k = 0; k < 12; k++) {
        float* w = o + 3 + k * 6;
        w[0] = sinf(p0 * f); w[1] = sinf(p1 * f); w[2] = sinf(p2 * f);
        w[3] = cosf(p0 * f); w[4] = cosf(p1 * f); w[5] = cosf(p2 * f);
        f *= 2.0f;
    }
    float d0 = xi[3], d1 = xi[4], d2 = xi[5];
    float* qv = f331 + (size_t)i * 331 + 256;
    qv[0] = d0; qv[1] = d1; qv[2] = d2;
    f = 1.0f;
    #pragma unroll
    for (int k = 0; k < 4; k++) {
        float* w = qv + 3 + k * 6;
        w[0] = sinf(d0 * f); w[1] = sinf(d1 * f); w[2] = sinf(d2 * f);
        w[3] = cosf(d0 * f); w[4] = cosf(d1 * f); w[5] = cosf(d2 * f);
        f *= 2.0f;
    }
    int app = (int)xi[6];
    const float* em = emb_a + (size_t)app * 48;
    float* eo = f331 + (size_t)i * 331 + 283;
    #pragma unroll
    for (int c = 0; c < 48; c++) eo[c] = em[c];
}

// ---------------- TF32 tensor-core GEMM (cp.async double-buffered) ----------
// CTA tile 128x128, BK=16, 2-stage pipeline, 8 warps 4(m)x2(n), warp 32x64.
// PRECISE=1: 3xTF32 hi/lo split computed at fragment-load time.

__device__ __forceinline__ uint32_t f2tf32(float v) {
    uint32_t u;
    asm("cvt.rna.tf32.f32 %0, %1;" : "=r"(u) : "f"(v));
    return u;
}

__device__ __forceinline__ void mma_tf32(float c[4], const uint32_t a[4],
                                         const uint32_t b[2]) {
    asm volatile(
        "mma.sync.aligned.m16n8k8.row.col.f32.tf32.tf32.f32 "
        "{%0,%1,%2,%3}, {%4,%5,%6,%7}, {%8,%9}, {%0,%1,%2,%3};\n"
        : "+f"(c[0]), "+f"(c[1]), "+f"(c[2]), "+f"(c[3])
        : "r"(a[0]), "r"(a[1]), "r"(a[2]), "r"(a[3]), "r"(b[0]), "r"(b[1]));
}

__device__ __forceinline__ uint32_t smem_u32(const void* p) {
    return (uint32_t)__cvta_generic_to_shared(p);
}

// A stage: [128][20] (m-major, stride 20 floats -> conflict-free frag loads)
// B stage: [16][136]
__device__ __forceinline__ void stage_load(
    float (*As)[20], float (*Bs)[136],
    const float* __restrict__ A, int lda,
    const float* __restrict__ B, int ldb,
    int M, int K, int m0, int n0, int k0, int tid)
{
    // A: thread t -> row m=t>>1, 8 consecutive k at (t&1)*8
    int m  = tid >> 1;
    int kb = (tid & 1) * 8;
    int gm = m0 + m;
    const float* ga = A + (size_t)(gm < M ? gm : 0) * lda + k0 + kb;
    uint32_t sa = smem_u32(&As[m][kb]);
    bool mok = (gm < M);
    #pragma unroll
    for (int j = 0; j < 8; j++) {
        int sz = (mok && (k0 + kb + j) < K) ? 4 : 0;
        asm volatile("cp.async.ca.shared.global [%0], [%1], 4, %2;\n"
                     :: "r"(sa + j * 4), "l"(ga + j), "r"(sz));
    }
    // B: 512 chunks of 16B; thread t -> chunks t, t+256
    #pragma unroll
    for (int c0 = 0; c0 < 2; c0++) {
        int c = tid + c0 * 256;
        int row = c >> 5;
        int col = (c & 31) * 4;
        int gk = k0 + row;
        const float* gb = B + (size_t)(gk < K ? gk : 0) * ldb + n0 + col;
        uint32_t sb = smem_u32(&Bs[row][col]);
        int sz = (gk < K) ? 16 : 0;
        asm volatile("cp.async.ca.shared.global [%0], [%1], 16, %2;\n"
                     :: "r"(sb), "l"(gb), "r"(sz));
    }
}

template<int PRECISE>
__device__ __forceinline__ void compute_stage(
    const float (*As)[20], const float (*Bs)[136],
    float acc[2][8][4], int wm, int wn, int gid, int tig)
{
    #pragma unroll
    for (int kk = 0; kk < 16; kk += 8) {
        float av[2][4];
        #pragma unroll
        for (int i = 0; i < 2; i++) {
            int m = wm + i * 16 + gid;
            av[i][0] = As[m][kk + tig];
            av[i][1] = As[m + 8][kk + tig];
            av[i][2] = As[m][kk + tig + 4];
            av[i][3] = As[m + 8][kk + tig + 4];
        }
        uint32_t ah[2][4], al[2][4];
        #pragma unroll
        for (int i = 0; i < 2; i++)
            #pragma unroll
            for (int r = 0; r < 4; r++) {
                ah[i][r] = f2tf32(av[i][r]);
                if (PRECISE)
                    al[i][r] = f2tf32(av[i][r] - __uint_as_float(ah[i][r]));
            }
        float bv[8][2];
        #pragma unroll
        for (int j = 0; j < 8; j++) {
            int n = wn + j * 8 + gid;
            bv[j][0] = Bs[kk + tig][n];
            bv[j][1] = Bs[kk + tig + 4][n];
        }
        #pragma unroll
        for (int j = 0; j < 8; j++) {
            uint32_t bh[2];
            bh[0] = f2tf32(bv[j][0]);
            bh[1] = f2tf32(bv[j][1]);
            if (PRECISE) {
                uint32_t bl[2];
                bl[0] = f2tf32(bv[j][0] - __uint_as_float(bh[0]));
                bl[1] = f2tf32(bv[j][1] - __uint_as_float(bh[1]));
                #pragma unroll
                for (int i = 0; i < 2; i++) {
                    mma_tf32(acc[i][j], al[i], bh);   // lo*hi
                    mma_tf32(acc[i][j], ah[i], bl);   // hi*lo
                }
            }
            #pragma unroll
            for (int i = 0; i < 2; i++)
                mma_tf32(acc[i][j], ah[i], bh);       // hi*hi
        }
    }
}

template<int PRECISE>
__device__ __forceinline__ void gemm_main(
    float (*As)[128][20], float (*Bs)[16][136],
    const float* __restrict__ A, int lda,
    const float* __restrict__ B, int ldb,
    const float* __restrict__ bias,
    float* __restrict__ C, int ldc,
    int M, int N, int K, int relu, int m0, int n0)
{
    int tid = threadIdx.x;
    int wid = tid >> 5, lane = tid & 31;
    int wm = (wid >> 1) * 32;
    int wn = (wid & 1) * 64;
    int gid = lane >> 2, tig = lane & 3;

    float acc[2][8][4] = {};
    int numK = (K + 15) >> 4;

    stage_load(As[0], Bs[0], A, lda, B, ldb, M, K, m0, n0, 0, tid);
    asm volatile("cp.async.commit_group;\n");

    for (int kt = 0; kt < numK; kt++) {
        if (kt + 1 < numK) {
            stage_load(As[(kt + 1) & 1], Bs[(kt + 1) & 1], A, lda, B, ldb,
                       M, K, m0, n0, (kt + 1) * 16, tid);
            asm volatile("cp.async.commit_group;\n");
            asm volatile("cp.async.wait_group 1;\n");
        } else {
            asm volatile("cp.async.wait_group 0;\n");
        }
        __syncthreads();
        compute_stage<PRECISE>(As[kt & 1], Bs[kt & 1], acc, wm, wn, gid, tig);
        __syncthreads();
    }

    // ---- epilogue: bias + optional relu ----
    #pragma unroll
    for (int i = 0; i < 2; i++) {
        int r0 = m0 + wm + i * 16 + gid;
        int r1 = r0 + 8;
        #pragma unroll
        for (int j = 0; j < 8; j++) {
            int col = n0 + wn + j * 8 + tig * 2;
            float b0v = (col < N) ? bias[col] : 0.0f;
            float b1v = (col + 1 < N) ? bias[col + 1] : 0.0f;
            if (r0 < M && col < N) {
                float v = acc[i][j][0] + b0v;
                if (relu) v = fmaxf(v, 0.0f);
                C[(size_t)r0 * ldc + col] = v;
            }
            if (r0 < M && col + 1 < N) {
                float v = acc[i][j][1] + b1v;
                if (relu) v = fmaxf(v, 0.0f);
                C[(size_t)r0 * ldc + col + 1] = v;
            }
            if (r1 < M && col < N) {
                float v = acc[i][j][2] + b0v;
                if (relu) v = fmaxf(v, 0.0f);
                C[(size_t)r1 * ldc + col] = v;
            }
            if (r1 < M && col + 1 < N) {
                float v = acc[i][j][3] + b1v;
                if (relu) v = fmaxf(v, 0.0f);
                C[(size_t)r1 * ldc + col + 1] = v;
            }
        }
    }
}

template<int PRECISE>
__global__ void __launch_bounds__(256, 2) mma_gemm_kernel(
    const float* __restrict__ A, int lda,
    const float* __restrict__ B, int ldb,
    const float* __restrict__ bias,
    float* __restrict__ C, int ldc,
    int M, int N, int K, int relu)
{
    __shared__ float As[2][128][20];
    __shared__ float Bs[2][16][136];
    gemm_main<PRECISE>(As, Bs, A, lda, B, ldb, bias, C, ldc, M, N, K, relu,
                       blockIdx.x * 128, blockIdx.y * 128);
}

// Grouped per-expert GEMM; fixed geometry, self-prunes against device counts.
__global__ void __launch_bounds__(256, 2) mma_moe_kernel(
    const float* __restrict__ Abase, int lda,
    const float* __restrict__ Bbase, long long bstride, int ldb,
    const float* __restrict__ biasBase, int biasStride,
    float* __restrict__ Cbase, int ldc,
    int Ncols, int K, int relu)
{
    int e = blockIdx.z;
    int Me = min(g_cnt[e], CAPE);
    int m0 = blockIdx.x * 128;
    if (m0 >= Me) return;
    __shared__ float As[2][128][20];
    __shared__ float Bs[2][16][136];
    const float* A = Abase + (size_t)e * CAPE * lda;
    float* C = Cbase + (size_t)e * CAPE * ldc;
    const float* B = Bbase + (size_t)e * bstride;
    const float* bias = biasBase + (size_t)e * biasStride;
    gemm_main<0>(As, Bs, A, lda, B, ldb, bias, C, ldc, Me, Ncols, K, relu,
                 m0, blockIdx.y * 128);
}

// ---------------- fused layernorm + gating (no writeback of normalized row) -
__global__ void ln_gate_kernel(const float* __restrict__ ext,
                               const float* __restrict__ g,
                               const float* __restrict__ b,
                               const float* __restrict__ wg,
                               int* __restrict__ eidx,
                               float* __restrict__ gate)
{
    int row = blockIdx.x;
    int tid = threadIdx.x;
    int lane = tid & 31, wid = tid >> 5;
    float v = ext[(size_t)row * 256 + tid];
    __shared__ float red[8];
    __shared__ float sh_mean, sh_rstd;
    float s = v;
    #pragma unroll
    for (int o = 16; o > 0; o >>= 1) s += __shfl_xor_sync(0xffffffffu, s, o);
    if (lane == 0) red[wid] = s;
    __syncthreads();
    if (tid == 0) {
        float t = 0.0f;
        #pragma unroll
        for (int i = 0; i < 8; i++) t += red[i];
        sh_mean = t * (1.0f / 256.0f);
    }
    __syncthreads();
    float d = v - sh_mean;
    float qv = d * d;
    #pragma unroll
    for (int o = 16; o > 0; o >>= 1) qv += __shfl_xor_sync(0xffffffffu, qv, o);
    if (lane == 0) red[wid] = qv;
    __syncthreads();
    if (tid == 0) {
        float t = 0.0f;
        #pragma unroll
        for (int i = 0; i < 8; i++) t += red[i];
        sh_rstd = rsqrtf(t * (1.0f / 256.0f) + 1e-5f);
    }
    __syncthreads();
    float nv = d * sh_rstd * g[tid] + b[tid];

    // logits = nv . wg  (8 experts)
    float c[8];
    #pragma unroll
    for (int e = 0; e < 8; e++) c[e] = nv * wg[tid * 8 + e];
    #pragma unroll
    for (int e = 0; e < 8; e++)
        #pragma unroll
        for (int o = 16; o > 0; o >>= 1) c[e] += __shfl_xor_sync(0xffffffffu, c[e], o);
    __shared__ float lg[8][8];
    if (lane == 0)
        #pragma unroll
        for (int e = 0; e < 8; e++) lg[wid][e] = c[e];
    __syncthreads();
    if (tid == 0) {
        float logit[8];
        #pragma unroll
        for (int e = 0; e < 8; e++) {
            float t = 0.0f;
            #pragma unroll
            for (int w = 0; w < 8; w++) t += lg[w][e];
            logit[e] = t;
        }
        int best = 0; float bv = logit[0];
        #pragma unroll
        for (int e = 1; e < 8; e++) if (logit[e] > bv) { bv = logit[e]; best = e; }
        float sum = 0.0f;
        #pragma unroll
        for (int e = 0; e < 8; e++) sum += expf(logit[e] - bv);
        eidx[row] = best;
        gate[row] = 1.0f / sum;
    }
}

// ---------------- deterministic per-expert ranking ---------------------------
__global__ void count_kernel(const int* __restrict__ eidx, int* __restrict__ ccnt)
{
    __shared__ int c[8];
    if (threadIdx.x < 8) c[threadIdx.x] = 0;
    __syncthreads();
    int base = blockIdx.x * 1024;
    for (int t = threadIdx.x; t < 1024; t += 256)
        atomicAdd(&c[eidx[base + t]], 1);
    __syncthreads();
    if (threadIdx.x < 8) ccnt[blockIdx.x * 8 + threadIdx.x] = c[threadIdx.x];
}

__global__ void scan_kernel(const int* __restrict__ ccnt, int* __restrict__ coff,
                            int* __restrict__ cnt)
{
    int e = threadIdx.x;
    int run = 0;
    for (int ch = 0; ch < NCHUNK; ch++) {
        coff[ch * 8 + e] = run;
        run += ccnt[ch * 8 + e];
    }
    cnt[e] = run;
}

__global__ void rank_kernel(const int* __restrict__ eidx,
                            const int* __restrict__ coff,
                            int* __restrict__ loc)
{
    __shared__ int se[1024];
    __shared__ int sl[1024];
    __shared__ int c[8];
    int base = blockIdx.x * 1024;
    for (int t = threadIdx.x; t < 1024; t += 256) se[t] = eidx[base + t];
    if (threadIdx.x < 8) c[threadIdx.x] = coff[blockIdx.x * 8 + threadIdx.x];
    __syncthreads();
    if (threadIdx.x == 0) {
        for (int t = 0; t < 1024; t++) { int e = se[t]; sl[t] = c[e]++; }
    }
    __syncthreads();
    for (int t = threadIdx.x; t < 1024; t += 256) loc[base + t] = sl[t];
}

// ---------------- dispatch ---------------------------------------------------
__global__ void dispatch_kernel(const float* __restrict__ H,
                                const int* __restrict__ eidx,
                                const int* __restrict__ loc,
                                float* __restrict__ disp)
{
    int token = blockIdx.x * 8 + (threadIdx.x >> 5);
    int lane = threadIdx.x & 31;
    int l = loc[token];
    if (l >= CAPE) return;
    int e = eidx[token];
    const float4* src = (const float4*)(H + (size_t)token * 256);
    float4* dst = (float4*)(disp + ((size_t)e * CAPE + l) * 512);
    dst[lane]      = src[lane];
    dst[lane + 32] = src[lane + 32];
}

// ---------------- gather + gate + relu + sigma -------------------------------
__global__ void gather_kernel(const float* __restrict__ Q,
                              const int* __restrict__ eidx,
                              const int* __restrict__ loc,
                              const float* __restrict__ gate,
                              const float* __restrict__ ws,
                              const float* __restrict__ bs,
                              float* __restrict__ HM,
                              float* __restrict__ out)
{
    int token = blockIdx.x * 8 + (threadIdx.x >> 5);
    int lane = threadIdx.x & 31;
    int l = loc[token];
    int e = eidx[token];
    float gv = gate[token];
    bool keep = (l < CAPE);
    const float* src = Q + ((size_t)e * CAPE + (keep ? l : 0)) * 256;
    float* dstrow = HM + (size_t)token * 256;
    float dot = 0.0f;
    for (int c = lane; c < 256; c += 32) {
        float v = keep ? src[c] * gv : 0.0f;
        v = fmaxf(v, 0.0f);
        dstrow[c] = v;
        dot += v * ws[c];
    }
    #pragma unroll
    for (int o = 16; o > 0; o >>= 1) dot += __shfl_xor_sync(0xffffffffu, dot, o);
    if (lane == 0) {
        float t = dot + bs[0];
        float sp = fmaxf(t, 0.0f) + log1pf(expf(-fabsf(t)));
        out[(size_t)token * 4 + 3] = sp;
    }
}

// ---------------- rgb --------------------------------------------------------
__global__ void rgb_kernel(const float* __restrict__ F,
                           const float* __restrict__ wc,
                           const float* __restrict__ bc,
                           float* __restrict__ out)
{
    int token = blockIdx.x * 8 + (threadIdx.x >> 5);
    int lane = threadIdx.x & 31;
    const float* row = F + (size_t)token * 128;
    float a0 = 0.0f, a1 = 0.0f, a2 = 0.0f;
    for (int c = lane; c < 128; c += 32) {
        float v = row[c];
        a0 += v * wc[c * 3 + 0];
        a1 += v * wc[c * 3 + 1];
        a2 += v * wc[c * 3 + 2];
    }
    #pragma unroll
    for (int o = 16; o > 0; o >>= 1) {
        a0 += __shfl_xor_sync(0xffffffffu, a0, o);
        a1 += __shfl_xor_sync(0xffffffffu, a1, o);
        a2 += __shfl_xor_sync(0xffffffffu, a2, o);
    }
    if (lane == 0) {
        out[(size_t)token * 4 + 0] = 1.0f / (1.0f + expf(-(a0 + bc[0])));
        out[(size_t)token * 4 + 1] = 1.0f / (1.0f + expf(-(a1 + bc[1])));
        out[(size_t)token * 4 + 2] = 1.0f / (1.0f + expf(-(a2 + bc[2])));
    }
}

// ============================================================================
extern "C" void kernel_launch(void* const* d_in, const int* in_sizes, int n_in,
                              void* d_out, int out_size)
{
    const float* x     = (const float*)d_in[0];
    const float* emb_a = (const float*)d_in[1];
    const float* w_xyz = (const float*)d_in[2];
    const float* b_xyz = (const float*)d_in[3];
    const float* wg1   = (const float*)d_in[4];
    const float* bg1   = (const float*)d_in[5];
    const float* wg2   = (const float*)d_in[6];
    const float* bg2   = (const float*)d_in[7];
    const float* ln_g  = (const float*)d_in[8];
    const float* ln_b  = (const float*)d_in[9];
    const float* wg    = (const float*)d_in[10];
    const float* eW_a  = (const float*)d_in[11];
    const float* eb_a  = (const float*)d_in[12];
    const float* eW3   = (const float*)d_in[13];
    const float* eb3   = (const float*)d_in[14];
    const float* eW_b  = (const float*)d_in[15];
    const float* eb_b  = (const float*)d_in[16];
    const float* w1    = (const float*)d_in[17];
    const float* b1    = (const float*)d_in[18];
    const float* w2    = (const float*)d_in[19];
    const float* b2    = (const float*)d_in[20];
    const float* ws    = (const float*)d_in[21];
    const float* bs    = (const float*)d_in[22];
    const float* wc    = (const float*)d_in[23];
    const float* bc    = (const float*)d_in[24];
    float* out = (float*)d_out;

    float *x75, *h, *t1, *ext, *disp, *p, *q, *f331, *f128, *gate;
    int *eidx, *loc, *ccnt, *coff, *cnt;
    cudaGetSymbolAddress((void**)&x75,  g_x75);
    cudaGetSymbolAddress((void**)&h,    g_h);
    cudaGetSymbolAddress((void**)&t1,   g_t1);
    cudaGetSymbolAddress((void**)&ext,  g_ext);
    cudaGetSymbolAddress((void**)&disp, g_disp);
    cudaGetSymbolAddress((void**)&p,    g_p);
    cudaGetSymbolAddress((void**)&q,    g_q);
    cudaGetSymbolAddress((void**)&f331, g_f331);
    cudaGetSymbolAddress((void**)&f128, g_f128);
    cudaGetSymbolAddress((void**)&gate, g_gate);
    cudaGetSymbolAddress((void**)&eidx, g_eidx);
    cudaGetSymbolAddress((void**)&loc,  g_loc);
    cudaGetSymbolAddress((void**)&ccnt, g_ccnt);
    cudaGetSymbolAddress((void**)&coff, g_coff);
    cudaGetSymbolAddress((void**)&cnt,  g_cnt);

    // 1) featurize
    featurize_kernel<<<NTOK / 256, 256>>>(x, emb_a, x75, f331);

    // 2) backbone GEMMs (gating-critical path -> 3xTF32 PRECISE)
    dim3 gBig(NTOK / 128, 2);   // (1024, 2)
    mma_gemm_kernel<1><<<gBig, 256>>>(x75, 75, w_xyz, 256, b_xyz, h,   256, NTOK, 256, 75,  0);
    mma_gemm_kernel<1><<<gBig, 256>>>(h,  256, wg1,   256, bg1,   t1,  256, NTOK, 256, 256, 1);
    mma_gemm_kernel<1><<<gBig, 256>>>(t1, 256, wg2,   256, bg2,   ext, 256, NTOK, 256, 256, 0);

    // 3) fused layernorm + gating
    ln_gate_kernel<<<NTOK, 256>>>(ext, ln_g, ln_b, wg, eidx, gate);

    // 4) deterministic ranking + dispatch
    count_kernel<<<NCHUNK, 256>>>(eidx, ccnt);
    scan_kernel<<<1, 8>>>(ccnt, coff, cnt);
    rank_kernel<<<NCHUNK, 256>>>(eidx, coff, loc);
    dispatch_kernel<<<NTOK / 8, 256>>>(h, eidx, loc, disp);

    // 5) expert MLP (grouped TF32 GEMMs)
    dim3 gMoe(CAPE / 128, 2, NEXP);  // (160, 2, 8)
    mma_moe_kernel<<<gMoe, 256>>>(disp, 512, eW_a + 0 * 65536, 3LL * 65536, 256,
                                  eb_a + 0 * 256, 768, p, 256, 256, 256, 1);
    mma_moe_kernel<<<gMoe, 256>>>(p, 256, eW_a + 1 * 65536, 3LL * 65536, 256,
                                  eb_a + 1 * 256, 768, q, 256, 256, 256, 1);
    mma_moe_kernel<<<gMoe, 256>>>(q, 256, eW_a + 2 * 65536, 3LL * 65536, 256,
                                  eb_a + 2 * 256, 768, disp + 256, 512, 256, 256, 1);
    mma_moe_kernel<<<gMoe, 256>>>(disp, 512, eW3, 512LL * 256, 256,
                                  eb3, 256, p, 256, 256, 512, 1);
    mma_moe_kernel<<<gMoe, 256>>>(p, 256, eW_b + 0 * 65536, 3LL * 65536, 256,
                                  eb_b + 0 * 256, 768, q, 256, 256, 256, 1);
    mma_moe_kernel<<<gMoe, 256>>>(q, 256, eW_b + 1 * 65536, 3LL * 65536, 256,
                                  eb_b + 1 * 256, 768, p, 256, 256, 256, 1);
    mma_moe_kernel<<<gMoe, 256>>>(p, 256, eW_b + 2 * 65536, 3LL * 65536, 256,
                                  eb_b + 2 * 256, 768, q, 256, 256, 256, 0);

    // 6) gather + gate + relu + sigma
    gather_kernel<<<NTOK / 8, 256>>>(q, eidx, loc, gate, ws, bs, h, out);

    // 7) head (FAST TF32)
    mma_gemm_kernel<0><<<gBig, 256>>>(h, 256, w1, 256, b1, f331, 331, NTOK, 256, 256, 0);
    dim3 g2(NTOK / 128, 1);
    mma_gemm_kernel<0><<<g2, 256>>>(f331, 331, w2, 128, b2, f128, 128, NTOK, 128, 331, 1);
    rgb_kernel<<<NTOK / 8, 256>>>(f128, wc, bc, out);
}